// round 9
// baseline (speedup 1.0000x reference)
#include <cuda_runtime.h>
#include <cuda_bf16.h>
#include <cstdint>
#include <cmath>

// Problem dims (fixed per reference)
#define T_DIM 512
#define N_DIM 1024
#define D_DIM 256
#define TN    (T_DIM * N_DIM)

// ---------------- device scratch (static, no allocations) ----------------
__device__ float g_e[TN];
__device__ float g_a[TN];
__device__ float g_b[TN];
__device__ __nv_bfloat16 g_bhi[D_DIM * D_DIM];  // fc_w hi bf16, [e][d] (K-major)
__device__ __nv_bfloat16 g_blo[D_DIM * D_DIM];  // fc_w lo bf16

// ---------------- small helpers ----------------
__device__ __forceinline__ uint32_t smem_u32(const void* p) {
    uint32_t a;
    asm("{ .reg .u64 t; cvta.to.shared.u64 t, %1; cvt.u32.u64 %0, t; }" : "=r"(a) : "l"(p));
    return a;
}
__device__ __forceinline__ void cp16(uint32_t dst, const void* src) {
    asm volatile("cp.async.cg.shared.global [%0], [%1], 16;" :: "r"(dst), "l"(src));
}
#define CP_COMMIT() asm volatile("cp.async.commit_group;" ::: "memory")
#define CP_WAIT0()  asm volatile("cp.async.wait_group 0;" ::: "memory")

#define LDSM_X4(r0, r1, r2, r3, addr) \
    asm volatile("ldmatrix.sync.aligned.m8n8.x4.shared.b16 {%0,%1,%2,%3}, [%4];" \
                 : "=r"(r0), "=r"(r1), "=r"(r2), "=r"(r3) : "r"(addr))
#define LDSM_X2(r0, r1, addr) \
    asm volatile("ldmatrix.sync.aligned.m8n8.x2.shared.b16 {%0,%1}, [%2];" \
                 : "=r"(r0), "=r"(r1) : "r"(addr))
#define MMA_BF16(d, a0, a1, a2, a3, b0, b1) \
    asm volatile("mma.sync.aligned.m16n8k16.row.col.f32.bf16.bf16.f32 " \
                 "{%0,%1,%2,%3},{%4,%5,%6,%7},{%8,%9},{%0,%1,%2,%3};" \
                 : "+f"((d)[0]), "+f"((d)[1]), "+f"((d)[2]), "+f"((d)[3]) \
                 : "r"(a0), "r"(a1), "r"(a2), "r"(a3), "r"(b0), "r"(b1))

// accurate tanh (fast-math-proof): 1 - 2/(e^{2x}+1), saturates correctly
__device__ __forceinline__ float tanh_acc(float x) {
    float ex = __expf(2.0f * x);
    return 1.0f - 2.0f / (ex + 1.0f);
}

// ---------------- kernel 0: split fc_w into bf16 hi/lo ----------------
__global__ void k_bconv(const float* __restrict__ w) {
    int i = blockIdx.x * 256 + threadIdx.x;
    float x = w[i];
    __nv_bfloat16 hi = __float2bfloat16(x);
    g_bhi[i] = hi;
    g_blo[i] = __float2bfloat16(x - __bfloat162float(hi));
}

// ---------------- kernel 1: scoring GEMM via mma.sync (split bf16) ----------------
// Block: 512 thr (16 warps), tile M=128 x N=256; warp tile Mw=64 x Nw=32.
// K in 4 chunks of 64 (fewer sync/drain boundaries), 2-stage cp.async pipeline.
// acc = Ah*Bh + Al*Bh + Ah*Bl  (fp32 acc, residual ~2^-16)
#define BM       128
#define BK       64
#define ASTRIDE  144                          // 128B data + 16B pad (36r mod 32 distinct)
#define A_BYTES  (128 * ASTRIDE)              // 18432
#define B_BYTES  (256 * ASTRIDE)              // 36864
#define STAGE    (2 * A_BYTES + 2 * B_BYTES)  // 110592
#define OFF_CONST (2 * STAGE)                 // 221184
#define SMEM_TOTAL (OFF_CONST + 2 * 256 * 4)  // 223232 (< 227KB limit)

__global__ __launch_bounds__(512, 1)
void k_score(const float* __restrict__ H,
             const float* __restrict__ fc_b,
             const float* __restrict__ score_w)
{
    extern __shared__ char smem[];
    const uint32_t sbase = smem_u32(smem);
    float* s_bias = (float*)(smem + OFF_CONST);
    float* s_sw   = (float*)(smem + OFF_CONST + 1024);
    float* s_part = (float*)smem;             // reused after last compute

    const int tid   = threadIdx.x;
    const int wid   = tid >> 5;
    const int lane  = tid & 31;
    const int warpM = wid >> 3;               // 0..1 : 64-row half
    const int warpN = wid & 7;                // 0..7 : 32-col group
    const int m0    = blockIdx.x * BM;

    if (tid < 256) { s_bias[tid] = fc_b[tid]; s_sw[tid] = score_w[tid]; }

    float acc[64];
    #pragma unroll
    for (int i = 0; i < 64; ++i) acc[i] = 0.0f;

    const int arow = tid >> 2;                // A loader: row 0..127
    const int aseg = tid & 3;                 // 8-float segment (x2 sub-chunks)

    auto load_B_async = [&](int st, int kc) {
        uint32_t bh = sbase + st * STAGE + 2 * A_BYTES;
        uint32_t bl = bh + B_BYTES;
        const char* ph = (const char*)g_bhi;
        const char* pl = (const char*)g_blo;
        #pragma unroll
        for (int i = 0; i < 4; ++i) {
            int cid = tid + i * 512;          // 0..2047
            int row = cid >> 3;               // 0..255
            int seg = cid & 7;
            size_t gb = (size_t)(row * D_DIM + kc * BK + seg * 8) * 2;
            uint32_t so = (uint32_t)(row * ASTRIDE + seg * 16);
            cp16(bh + so, ph + gb);
            cp16(bl + so, pl + gb);
        }
    };
    auto load_A_regs = [&](int kc, float4 (&r)[2][2]) {
        #pragma unroll
        for (int j = 0; j < 2; ++j) {
            const float* p = &H[(size_t)(m0 + arow) * D_DIM + kc * BK + j * 32 + aseg * 8];
            r[j][0] = *(const float4*)p;
            r[j][1] = *(const float4*)(p + 4);
        }
    };
    auto store_A = [&](int st, float4 (&r)[2][2]) {
        #pragma unroll
        for (int j = 0; j < 2; ++j) {
            float v[8] = {r[j][0].x, r[j][0].y, r[j][0].z, r[j][0].w,
                          r[j][1].x, r[j][1].y, r[j][1].z, r[j][1].w};
            uint32_t uh[4], ul[4];
            #pragma unroll
            for (int q = 0; q < 4; ++q) {
                __nv_bfloat16 h0 = __float2bfloat16(v[2*q]);
                __nv_bfloat16 h1 = __float2bfloat16(v[2*q+1]);
                float l0 = v[2*q]   - __bfloat162float(h0);
                float l1 = v[2*q+1] - __bfloat162float(h1);
                __nv_bfloat162 hh = __nv_bfloat162(h0, h1);
                __nv_bfloat162 ll = __nv_bfloat162(__float2bfloat16(l0), __float2bfloat16(l1));
                uh[q] = *(uint32_t*)&hh;
                ul[q] = *(uint32_t*)&ll;
            }
            char* ah = smem + st * STAGE + arow * ASTRIDE + j * 64 + aseg * 16;
            *(uint4*)ah             = make_uint4(uh[0], uh[1], uh[2], uh[3]);
            *(uint4*)(ah + A_BYTES) = make_uint4(ul[0], ul[1], ul[2], ul[3]);
        }
    };
    auto compute = [&](int st) {
        uint32_t a_base = sbase + st * STAGE;
        uint32_t b_hi   = a_base + 2 * A_BYTES;
        uint32_t b_lo   = b_hi + B_BYTES;
        #pragma unroll
        for (int ks = 0; ks < 4; ++ks) {      // 4 x k16 within the 64-K chunk
            uint32_t bh[4][2], bl[4][2];
            #pragma unroll
            for (int nt = 0; nt < 4; ++nt) {
                uint32_t brow = (uint32_t)(warpN * 32 + nt * 8 + (lane & 7));
                uint32_t boff = brow * ASTRIDE + ks * 32 + ((lane >> 3) & 1) * 16;
                LDSM_X2(bh[nt][0], bh[nt][1], b_hi + boff);
                LDSM_X2(bl[nt][0], bl[nt][1], b_lo + boff);
            }
            #pragma unroll
            for (int mt = 0; mt < 4; ++mt) {
                uint32_t arf = (uint32_t)(warpM * 64 + mt * 16 + (lane & 15));
                uint32_t aoff = arf * ASTRIDE + ks * 32 + (lane >> 4) * 16;
                uint32_t ah0, ah1, ah2, ah3, al0, al1, al2, al3;
                LDSM_X4(ah0, ah1, ah2, ah3, a_base + aoff);
                LDSM_X4(al0, al1, al2, al3, a_base + A_BYTES + aoff);
                #pragma unroll
                for (int nt = 0; nt < 4; ++nt) {
                    float* d = &acc[(mt * 4 + nt) * 4];
                    MMA_BF16(d, ah0, ah1, ah2, ah3, bh[nt][0], bh[nt][1]);
                    MMA_BF16(d, al0, al1, al2, al3, bh[nt][0], bh[nt][1]);
                    MMA_BF16(d, ah0, ah1, ah2, ah3, bl[nt][0], bl[nt][1]);
                }
            }
        }
    };

    // ---- prologue ----
    {
        load_B_async(0, 0);
        CP_COMMIT();
        float4 r[2][2];
        load_A_regs(0, r);
        store_A(0, r);
        CP_WAIT0();
        __syncthreads();
    }
    // ---- mainloop: 4 chunks, 2-stage ----
    #pragma unroll
    for (int kc = 0; kc < 4; ++kc) {
        const int st = kc & 1;
        float4 p[2][2];
        if (kc < 3) {
            load_B_async(st ^ 1, kc + 1);
            CP_COMMIT();
            load_A_regs(kc + 1, p);
        }
        compute(st);
        if (kc < 3) {
            store_A(st ^ 1, p);
            CP_WAIT0();
        }
        __syncthreads();
    }

    // ---- epilogue: bias + tanh + dot(score_w); smem cross-warp reduce ----
    #pragma unroll
    for (int mt = 0; mt < 4; ++mt) {
        float e0 = 0.0f, e1 = 0.0f;
        #pragma unroll
        for (int nt = 0; nt < 4; ++nt) {
            int col = warpN * 32 + nt * 8 + (lane & 3) * 2;
            float b0 = s_bias[col], b1 = s_bias[col + 1];
            float w0 = s_sw[col],   w1 = s_sw[col + 1];
            float* d = &acc[(mt * 4 + nt) * 4];
            e0 = fmaf(tanh_acc(d[0] + b0), w0, e0);
            e0 = fmaf(tanh_acc(d[1] + b1), w1, e0);
            e1 = fmaf(tanh_acc(d[2] + b0), w0, e1);
            e1 = fmaf(tanh_acc(d[3] + b1), w1, e1);
        }
        e0 += __shfl_xor_sync(0xFFFFFFFFu, e0, 1);
        e0 += __shfl_xor_sync(0xFFFFFFFFu, e0, 2);
        e1 += __shfl_xor_sync(0xFFFFFFFFu, e1, 1);
        e1 += __shfl_xor_sync(0xFFFFFFFFu, e1, 2);
        if ((lane & 3) == 0) {
            int r = warpM * 64 + mt * 16 + (lane >> 2);
            s_part[warpN * 128 + r]     = e0;
            s_part[warpN * 128 + r + 8] = e1;
        }
    }
    __syncthreads();
    if (tid < 128) {
        float s = 0.0f;
        #pragma unroll
        for (int w = 0; w < 8; ++w) s += s_part[w * 128 + tid];
        g_e[m0 + tid] = s;
    }
}

// ---------------- kernel 2: parallel online-softmax scan (warp per column) ----------------
__global__ __launch_bounds__(256) void k_scan() {
    const int wid  = threadIdx.x >> 5;
    const int lane = threadIdx.x & 31;
    const int n    = blockIdx.x * 8 + wid;      // 128 blocks x 8 warps = 1024 cols
    const int t0   = lane * 16;

    float ev[16];
    #pragma unroll
    for (int k = 0; k < 16; ++k) ev[k] = g_e[(t0 + k) * N_DIM + n];

    float m = -INFINITY, s = 0.0f;
    #pragma unroll
    for (int k = 0; k < 16; ++k) {
        float e  = ev[k];
        float mn = fmaxf(m, e);
        s = s * __expf(m - mn) + __expf(e - mn);
        m = mn;
    }
    float im = m, is = s;
    #pragma unroll
    for (int off = 1; off < 32; off <<= 1) {
        float om = __shfl_up_sync(0xFFFFFFFFu, im, off);
        float os = __shfl_up_sync(0xFFFFFFFFu, is, off);
        if (lane >= off) {
            float mn = fmaxf(om, im);
            is = os * __expf(om - mn) + is * __expf(im - mn);
            im = mn;
        }
    }
    float Em = __shfl_up_sync(0xFFFFFFFFu, im, 1);
    float Es = __shfl_up_sync(0xFFFFFFFFu, is, 1);
    if (lane == 0) { Em = -INFINITY; Es = 0.0f; }

    float mc = Em, sc = Es;
    #pragma unroll
    for (int k = 0; k < 16; ++k) {
        float e   = ev[k];
        float mn  = fmaxf(mc, e);
        float al  = __expf(mc - mn);
        float p   = __expf(e - mn);
        float sn  = sc * al + p;
        float inv = 1.0f / sn;
        int idx = (t0 + k) * N_DIM + n;
        g_a[idx] = sc * al * inv;
        g_b[idx] = p * inv;
        mc = mn; sc = sn;
    }
}

// ---------------- kernel 3: streaming recurrence apply (scalar/thread) ----------------
// One block (256 thr) per column n; one thread per (n, d). Streaming cache
// hints: H read-once (__ldcs), out write-streaming (__stcs), a/b broadcast (__ldg).
__global__ __launch_bounds__(256) void k_apply(
    const float* __restrict__ H, float* __restrict__ out)
{
    const int n = blockIdx.x;
    const int d = threadIdx.x;                      // 0..255
    const size_t base  = (size_t)n * D_DIM + d;
    const size_t tstep = (size_t)N_DIM * D_DIM;     // per-t stride in floats

    float c = 0.0f;
    for (int t = 0; t < T_DIM; t += 8) {
        const int ia = t * N_DIM + n;
        float a[8], b[8], h[8];
        #pragma unroll
        for (int j = 0; j < 8; ++j) {
            a[j] = __ldg(&g_a[ia + j * N_DIM]);     // uniform per block (broadcast)
            b[j] = __ldg(&g_b[ia + j * N_DIM]);
        }
        #pragma unroll
        for (int j = 0; j < 8; ++j)
            h[j] = __ldcs(&H[base + (size_t)(t + j) * tstep]);
        #pragma unroll
        for (int j = 0; j < 8; ++j) {
            c = fmaf(a[j], c, b[j] * h[j]);
            __stcs(&out[base + (size_t)(t + j) * tstep], c);
        }
    }
}

// ---------------- launch ----------------
extern "C" void kernel_launch(void* const* d_in, const int* in_sizes, int n_in,
                              void* d_out, int out_size) {
    const float* H       = (const float*)d_in[0];
    const float* fc_w    = (const float*)d_in[1];
    const float* fc_b    = (const float*)d_in[2];
    const float* score_w = (const float*)d_in[3];
    float* out = (float*)d_out;

    cudaFuncSetAttribute(k_score, cudaFuncAttributeMaxDynamicSharedMemorySize, SMEM_TOTAL);

    k_bconv<<<D_DIM * D_DIM / 256, 256>>>(fc_w);
    k_score<<<TN / BM, 512, SMEM_TOTAL>>>(H, fc_b, score_w);
    k_scan<<<128, 256>>>();
    k_apply<<<N_DIM, 256>>>(H, out);
}

// round 10
// speedup vs baseline: 1.5770x; 1.5770x over previous
#include <cuda_runtime.h>
#include <cuda_fp16.h>
#include <cstdint>
#include <cmath>

// Problem dims (fixed per reference)
#define T_DIM 512
#define N_DIM 1024
#define D_DIM 256
#define TN    (T_DIM * N_DIM)

// ---------------- device scratch (static, no allocations) ----------------
__device__ float g_e[TN];
__device__ float g_a[TN];
__device__ float g_b[TN];
__device__ __half g_bh[D_DIM * D_DIM];   // fc_w in fp16, [e][d] (K-major)

// ---------------- small helpers ----------------
__device__ __forceinline__ uint32_t smem_u32(const void* p) {
    uint32_t a;
    asm("{ .reg .u64 t; cvta.to.shared.u64 t, %1; cvt.u32.u64 %0, t; }" : "=r"(a) : "l"(p));
    return a;
}
__device__ __forceinline__ void cp16(uint32_t dst, const void* src) {
    asm volatile("cp.async.cg.shared.global [%0], [%1], 16;" :: "r"(dst), "l"(src));
}
#define CP_COMMIT() asm volatile("cp.async.commit_group;" ::: "memory")
#define CP_WAIT0()  asm volatile("cp.async.wait_group 0;" ::: "memory")
#define CP_WAIT1()  asm volatile("cp.async.wait_group 1;" ::: "memory")

#define LDSM_X4(r0, r1, r2, r3, addr) \
    asm volatile("ldmatrix.sync.aligned.m8n8.x4.shared.b16 {%0,%1,%2,%3}, [%4];" \
                 : "=r"(r0), "=r"(r1), "=r"(r2), "=r"(r3) : "r"(addr))
#define LDSM_X2(r0, r1, addr) \
    asm volatile("ldmatrix.sync.aligned.m8n8.x2.shared.b16 {%0,%1}, [%2];" \
                 : "=r"(r0), "=r"(r1) : "r"(addr))
#define MMA_FP16(d, a0, a1, a2, a3, b0, b1) \
    asm volatile("mma.sync.aligned.m16n8k16.row.col.f32.f16.f16.f32 " \
                 "{%0,%1,%2,%3},{%4,%5,%6,%7},{%8,%9},{%0,%1,%2,%3};" \
                 : "+f"((d)[0]), "+f"((d)[1]), "+f"((d)[2]), "+f"((d)[3]) \
                 : "r"(a0), "r"(a1), "r"(a2), "r"(a3), "r"(b0), "r"(b1))

// accurate tanh (fast-math-proof): 1 - 2/(e^{2x}+1), saturates correctly
__device__ __forceinline__ float tanh_acc(float x) {
    float ex = __expf(2.0f * x);
    return 1.0f - 2.0f / (ex + 1.0f);
}

// ---------------- kernel 0: convert fc_w to fp16 ----------------
__global__ void k_bconv(const float* __restrict__ w) {
    int i = blockIdx.x * 256 + threadIdx.x;
    g_bh[i] = __float2half_rn(w[i]);
}

// ---------------- kernel 1: scoring GEMM via mma.sync (fp16) ----------------
// Block: 512 thr (16 warps), tile M=128 x N=256; warp tile Mw=64 x Nw=32.
// K in 8 chunks of 32; 3-stage cp.async pipeline.
// Single fp16 MMA per k16 (error ~2^-11 on Q -> output rel_err ~1e-4).
#define BM       128
#define BK       32
#define ASTRIDE  80                           // 64B data + 16B pad per row
#define A_BYTES  (128 * ASTRIDE)              // 10240
#define B_BYTES  (256 * ASTRIDE)              // 20480
#define STAGE    (A_BYTES + B_BYTES)          // 30720
#define NSTAGE   3
#define OFF_CONST (NSTAGE * STAGE)            // 92160
#define SMEM_TOTAL (OFF_CONST + 2 * 256 * 4)  // 94208

__global__ __launch_bounds__(512, 1)
void k_score(const float* __restrict__ H,
             const float* __restrict__ fc_b,
             const float* __restrict__ score_w)
{
    extern __shared__ char smem[];
    const uint32_t sbase = smem_u32(smem);
    float* s_bias = (float*)(smem + OFF_CONST);
    float* s_sw   = (float*)(smem + OFF_CONST + 1024);
    float* s_part = (float*)smem;             // reused after last compute

    const int tid   = threadIdx.x;
    const int wid   = tid >> 5;
    const int lane  = tid & 31;
    const int warpM = wid >> 3;               // 0..1 : 64-row half
    const int warpN = wid & 7;                // 0..7 : 32-col group
    const int m0    = blockIdx.x * BM;

    if (tid < 256) { s_bias[tid] = fc_b[tid]; s_sw[tid] = score_w[tid]; }

    float acc[64];
    #pragma unroll
    for (int i = 0; i < 64; ++i) acc[i] = 0.0f;

    const int arow = tid >> 2;                // A loader: row 0..127
    const int aseg = tid & 3;                 // 8-float segment within 32-k chunk

    auto load_B_async = [&](int st, int kc) {
        uint32_t bh = sbase + st * STAGE + A_BYTES;
        const char* ph = (const char*)g_bh;
        #pragma unroll
        for (int i = 0; i < 2; ++i) {
            int cid = tid + i * 512;          // 0..1023
            int row = cid >> 2;               // 0..255
            int seg = cid & 3;
            size_t gb = (size_t)(row * D_DIM + kc * BK + seg * 8) * 2;
            uint32_t so = (uint32_t)(row * ASTRIDE + seg * 16);
            cp16(bh + so, ph + gb);
        }
    };
    auto load_A_regs = [&](int kc, float4& r0, float4& r1) {
        const float* p = &H[(size_t)(m0 + arow) * D_DIM + kc * BK + aseg * 8];
        r0 = *(const float4*)p;
        r1 = *(const float4*)(p + 4);
    };
    auto store_A = [&](int st, float4 r0, float4 r1) {
        uint32_t uh[4];
        __half2 h0 = __floats2half2_rn(r0.x, r0.y);
        __half2 h1 = __floats2half2_rn(r0.z, r0.w);
        __half2 h2 = __floats2half2_rn(r1.x, r1.y);
        __half2 h3 = __floats2half2_rn(r1.z, r1.w);
        uh[0] = *(uint32_t*)&h0; uh[1] = *(uint32_t*)&h1;
        uh[2] = *(uint32_t*)&h2; uh[3] = *(uint32_t*)&h3;
        char* ah = smem + st * STAGE + arow * ASTRIDE + aseg * 16;
        *(uint4*)ah = make_uint4(uh[0], uh[1], uh[2], uh[3]);
    };
    auto compute = [&](int st) {
        uint32_t a_base = sbase + st * STAGE;
        uint32_t b_base = a_base + A_BYTES;
        #pragma unroll
        for (int ks = 0; ks < 2; ++ks) {
            uint32_t bh[4][2];
            #pragma unroll
            for (int nt = 0; nt < 4; ++nt) {
                uint32_t brow = (uint32_t)(warpN * 32 + nt * 8 + (lane & 7));
                uint32_t boff = brow * ASTRIDE + ks * 32 + ((lane >> 3) & 1) * 16;
                LDSM_X2(bh[nt][0], bh[nt][1], b_base + boff);
            }
            #pragma unroll
            for (int mt = 0; mt < 4; ++mt) {
                uint32_t arf = (uint32_t)(warpM * 64 + mt * 16 + (lane & 15));
                uint32_t aoff = arf * ASTRIDE + ks * 32 + (lane >> 4) * 16;
                uint32_t a0, a1, a2, a3;
                LDSM_X4(a0, a1, a2, a3, a_base + aoff);
                #pragma unroll
                for (int nt = 0; nt < 4; ++nt)
                    MMA_FP16((&acc[(mt * 4 + nt) * 4]), a0, a1, a2, a3,
                             bh[nt][0], bh[nt][1]);
            }
        }
    };

    // ---- prologue: chunks 0 and 1 into stages 0 and 1 ----
    {
        float4 r0, r1;
        load_B_async(0, 0); CP_COMMIT();
        load_A_regs(0, r0, r1); store_A(0, r0, r1);
        load_B_async(1, 1); CP_COMMIT();
        load_A_regs(1, r0, r1); store_A(1, r0, r1);
        CP_WAIT1();                       // chunk 0's B resident; chunk 1 in flight
        __syncthreads();
    }

    // ---- mainloop: 3-stage rotation ----
    #pragma unroll
    for (int kc = 0; kc < 8; ++kc) {
        const int st = kc % NSTAGE;
        float4 p0, p1;
        if (kc + 2 < 8) {
            const int st2 = (kc + 2) % NSTAGE;
            load_B_async(st2, kc + 2); CP_COMMIT();
            load_A_regs(kc + 2, p0, p1);
            compute(st);
            store_A(st2, p0, p1);
            CP_WAIT1();
        } else {
            compute(st);
            CP_WAIT0();
        }
        __syncthreads();
    }

    // ---- epilogue: bias + tanh + dot(score_w); smem cross-warp reduce ----
    #pragma unroll
    for (int mt = 0; mt < 4; ++mt) {
        float e0 = 0.0f, e1 = 0.0f;
        #pragma unroll
        for (int nt = 0; nt < 4; ++nt) {
            int col = warpN * 32 + nt * 8 + (lane & 3) * 2;
            float b0 = s_bias[col], b1 = s_bias[col + 1];
            float w0 = s_sw[col],   w1 = s_sw[col + 1];
            float* d = &acc[(mt * 4 + nt) * 4];
            e0 = fmaf(tanh_acc(d[0] + b0), w0, e0);
            e0 = fmaf(tanh_acc(d[1] + b1), w1, e0);
            e1 = fmaf(tanh_acc(d[2] + b0), w0, e1);
            e1 = fmaf(tanh_acc(d[3] + b1), w1, e1);
        }
        e0 += __shfl_xor_sync(0xFFFFFFFFu, e0, 1);
        e0 += __shfl_xor_sync(0xFFFFFFFFu, e0, 2);
        e1 += __shfl_xor_sync(0xFFFFFFFFu, e1, 1);
        e1 += __shfl_xor_sync(0xFFFFFFFFu, e1, 2);
        if ((lane & 3) == 0) {
            int r = warpM * 64 + mt * 16 + (lane >> 2);
            s_part[warpN * 128 + r]     = e0;
            s_part[warpN * 128 + r + 8] = e1;
        }
    }
    __syncthreads();
    if (tid < 128) {
        float s = 0.0f;
        #pragma unroll
        for (int w = 0; w < 8; ++w) s += s_part[w * 128 + tid];
        g_e[m0 + tid] = s;
    }
}

// ---------------- kernel 2: parallel online-softmax scan (warp per column) ----------------
__global__ __launch_bounds__(256) void k_scan() {
    const int wid  = threadIdx.x >> 5;
    const int lane = threadIdx.x & 31;
    const int n    = blockIdx.x * 8 + wid;      // 128 blocks x 8 warps = 1024 cols
    const int t0   = lane * 16;

    float ev[16];
    #pragma unroll
    for (int k = 0; k < 16; ++k) ev[k] = g_e[(t0 + k) * N_DIM + n];

    float m = -INFINITY, s = 0.0f;
    #pragma unroll
    for (int k = 0; k < 16; ++k) {
        float e  = ev[k];
        float mn = fmaxf(m, e);
        s = s * __expf(m - mn) + __expf(e - mn);
        m = mn;
    }
    float im = m, is = s;
    #pragma unroll
    for (int off = 1; off < 32; off <<= 1) {
        float om = __shfl_up_sync(0xFFFFFFFFu, im, off);
        float os = __shfl_up_sync(0xFFFFFFFFu, is, off);
        if (lane >= off) {
            float mn = fmaxf(om, im);
            is = os * __expf(om - mn) + is * __expf(im - mn);
            im = mn;
        }
    }
    float Em = __shfl_up_sync(0xFFFFFFFFu, im, 1);
    float Es = __shfl_up_sync(0xFFFFFFFFu, is, 1);
    if (lane == 0) { Em = -INFINITY; Es = 0.0f; }

    float mc = Em, sc = Es;
    #pragma unroll
    for (int k = 0; k < 16; ++k) {
        float e   = ev[k];
        float mn  = fmaxf(mc, e);
        float al  = __expf(mc - mn);
        float p   = __expf(e - mn);
        float sn  = sc * al + p;
        float inv = 1.0f / sn;
        int idx = (t0 + k) * N_DIM + n;
        g_a[idx] = sc * al * inv;
        g_b[idx] = p * inv;
        mc = mn; sc = sn;
    }
}

// ---------------- kernel 3: streaming recurrence apply (scalar/thread) ----------------
// R8-verified version: one block (256 thr) per column n; one thread per (n, d).
__global__ __launch_bounds__(256) void k_apply(
    const float* __restrict__ H, float* __restrict__ out)
{
    const int n = blockIdx.x;
    const int d = threadIdx.x;                      // 0..255
    const size_t base  = (size_t)n * D_DIM + d;
    const size_t tstep = (size_t)N_DIM * D_DIM;     // per-t stride in floats

    float c = 0.0f;
    for (int t = 0; t < T_DIM; t += 8) {
        const int ia = t * N_DIM + n;
        float a[8], b[8], h[8];
        #pragma unroll
        for (int j = 0; j < 8; ++j) {
            a[j] = g_a[ia + j * N_DIM];             // uniform per block (broadcast)
            b[j] = g_b[ia + j * N_DIM];
        }
        #pragma unroll
        for (int j = 0; j < 8; ++j)
            h[j] = H[base + (size_t)(t + j) * tstep];
        #pragma unroll
        for (int j = 0; j < 8; ++j) {
            c = fmaf(a[j], c, b[j] * h[j]);
            out[base + (size_t)(t + j) * tstep] = c;
        }
    }
}

// ---------------- launch ----------------
extern "C" void kernel_launch(void* const* d_in, const int* in_sizes, int n_in,
                              void* d_out, int out_size) {
    const float* H       = (const float*)d_in[0];
    const float* fc_w    = (const float*)d_in[1];
    const float* fc_b    = (const float*)d_in[2];
    const float* score_w = (const float*)d_in[3];
    float* out = (float*)d_out;

    cudaFuncSetAttribute(k_score, cudaFuncAttributeMaxDynamicSharedMemorySize, SMEM_TOTAL);

    k_bconv<<<D_DIM * D_DIM / 256, 256>>>(fc_w);
    k_score<<<TN / BM, 512, SMEM_TOTAL>>>(H, fc_b, score_w);
    k_scan<<<128, 256>>>();
    k_apply<<<N_DIM, 256>>>(H, out);
}

// round 11
// speedup vs baseline: 1.6223x; 1.0287x over previous
#include <cuda_runtime.h>
#include <cuda_fp16.h>
#include <cstdint>
#include <cmath>

// Problem dims (fixed per reference)
#define T_DIM 512
#define N_DIM 1024
#define D_DIM 256
#define TN    (T_DIM * N_DIM)

// ---------------- device scratch (static, no allocations) ----------------
__device__ float g_e[TN];
__device__ float g_a[TN];
__device__ float g_b[TN];
__device__ __half g_bh[D_DIM * D_DIM];   // fc_w in fp16, [e][d] (K-major)

// ---------------- small helpers ----------------
__device__ __forceinline__ uint32_t smem_u32(const void* p) {
    uint32_t a;
    asm("{ .reg .u64 t; cvta.to.shared.u64 t, %1; cvt.u32.u64 %0, t; }" : "=r"(a) : "l"(p));
    return a;
}
__device__ __forceinline__ void cp16(uint32_t dst, const void* src) {
    asm volatile("cp.async.cg.shared.global [%0], [%1], 16;" :: "r"(dst), "l"(src));
}
#define CP_COMMIT() asm volatile("cp.async.commit_group;" ::: "memory")
#define CP_WAIT0()  asm volatile("cp.async.wait_group 0;" ::: "memory")
#define CP_WAIT1()  asm volatile("cp.async.wait_group 1;" ::: "memory")

#define LDSM_X4(r0, r1, r2, r3, addr) \
    asm volatile("ldmatrix.sync.aligned.m8n8.x4.shared.b16 {%0,%1,%2,%3}, [%4];" \
                 : "=r"(r0), "=r"(r1), "=r"(r2), "=r"(r3) : "r"(addr))
#define LDSM_X2(r0, r1, addr) \
    asm volatile("ldmatrix.sync.aligned.m8n8.x2.shared.b16 {%0,%1}, [%2];" \
                 : "=r"(r0), "=r"(r1) : "r"(addr))
#define MMA_FP16(d, a0, a1, a2, a3, b0, b1) \
    asm volatile("mma.sync.aligned.m16n8k16.row.col.f32.f16.f16.f32 " \
                 "{%0,%1,%2,%3},{%4,%5,%6,%7},{%8,%9},{%0,%1,%2,%3};" \
                 : "+f"((d)[0]), "+f"((d)[1]), "+f"((d)[2]), "+f"((d)[3]) \
                 : "r"(a0), "r"(a1), "r"(a2), "r"(a3), "r"(b0), "r"(b1))

// accurate tanh (fast-math-proof): 1 - 2/(e^{2x}+1), saturates correctly
__device__ __forceinline__ float tanh_acc(float x) {
    float ex = __expf(2.0f * x);
    return 1.0f - 2.0f / (ex + 1.0f);
}

// ---------------- kernel 0: convert fc_w to fp16 ----------------
__global__ void k_bconv(const float* __restrict__ w) {
    int i = blockIdx.x * 256 + threadIdx.x;
    g_bh[i] = __float2half_rn(w[i]);
}

// ---------------- kernel 1: scoring GEMM via mma.sync (fp16) ----------------
// Block: 256 thr (8 warps), tile M=64 x N=256; warp tile Mw=64 x Nw=32.
// 2 CTAs/SM (cross-CTA latency hiding); K in 8 chunks of 32; 3-stage pipeline.
#define BM       64
#define BK       32
#define ASTRIDE  80                           // 64B data + 16B pad per row
#define A_BYTES  (64 * ASTRIDE)               // 5120
#define B_BYTES  (256 * ASTRIDE)              // 20480
#define STAGE    (A_BYTES + B_BYTES)          // 25600
#define NSTAGE   3
#define OFF_CONST (NSTAGE * STAGE)            // 76800
#define SMEM_TOTAL (OFF_CONST + 2 * 256 * 4)  // 78848  (x2 CTAs = 157696 < 228KB)

__global__ __launch_bounds__(256, 2)
void k_score(const float* __restrict__ H,
             const float* __restrict__ fc_b,
             const float* __restrict__ score_w)
{
    extern __shared__ char smem[];
    const uint32_t sbase = smem_u32(smem);
    float* s_bias = (float*)(smem + OFF_CONST);
    float* s_sw   = (float*)(smem + OFF_CONST + 1024);
    float* s_part = (float*)smem;             // reused after last compute

    const int tid  = threadIdx.x;
    const int wid  = tid >> 5;                // warp owns cols [wid*32, wid*32+32)
    const int lane = tid & 31;
    const int m0   = blockIdx.x * BM;

    s_bias[tid] = fc_b[tid];
    s_sw[tid]   = score_w[tid];

    float acc[64];                            // [mt 0..3][nt 0..3][4]
    #pragma unroll
    for (int i = 0; i < 64; ++i) acc[i] = 0.0f;

    const int arow = tid >> 2;                // A loader: row 0..63
    const int aseg = tid & 3;                 // 8-float segment within 32-k chunk

    auto load_B_async = [&](int st, int kc) {
        uint32_t bh = sbase + st * STAGE + A_BYTES;
        const char* ph = (const char*)g_bh;
        #pragma unroll
        for (int i = 0; i < 4; ++i) {
            int cid = tid + i * 256;          // 0..1023
            int row = cid >> 2;               // 0..255
            int seg = cid & 3;
            size_t gb = (size_t)(row * D_DIM + kc * BK + seg * 8) * 2;
            uint32_t so = (uint32_t)(row * ASTRIDE + seg * 16);
            cp16(bh + so, ph + gb);
        }
    };
    auto load_A_regs = [&](int kc, float4& r0, float4& r1) {
        const float* p = &H[(size_t)(m0 + arow) * D_DIM + kc * BK + aseg * 8];
        r0 = *(const float4*)p;
        r1 = *(const float4*)(p + 4);
    };
    auto store_A = [&](int st, float4 r0, float4 r1) {
        uint32_t uh[4];
        __half2 h0 = __floats2half2_rn(r0.x, r0.y);
        __half2 h1 = __floats2half2_rn(r0.z, r0.w);
        __half2 h2 = __floats2half2_rn(r1.x, r1.y);
        __half2 h3 = __floats2half2_rn(r1.z, r1.w);
        uh[0] = *(uint32_t*)&h0; uh[1] = *(uint32_t*)&h1;
        uh[2] = *(uint32_t*)&h2; uh[3] = *(uint32_t*)&h3;
        char* ah = smem + st * STAGE + arow * ASTRIDE + aseg * 16;
        *(uint4*)ah = make_uint4(uh[0], uh[1], uh[2], uh[3]);
    };
    auto compute = [&](int st) {
        uint32_t a_base = sbase + st * STAGE;
        uint32_t b_base = a_base + A_BYTES;
        #pragma unroll
        for (int ks = 0; ks < 2; ++ks) {
            uint32_t bh[4][2];
            #pragma unroll
            for (int nt = 0; nt < 4; ++nt) {
                uint32_t brow = (uint32_t)(wid * 32 + nt * 8 + (lane & 7));
                uint32_t boff = brow * ASTRIDE + ks * 32 + ((lane >> 3) & 1) * 16;
                LDSM_X2(bh[nt][0], bh[nt][1], b_base + boff);
            }
            #pragma unroll
            for (int mt = 0; mt < 4; ++mt) {
                uint32_t aoff = (uint32_t)((mt * 16 + (lane & 15)) * ASTRIDE
                                           + ks * 32 + (lane >> 4) * 16);
                uint32_t a0, a1, a2, a3;
                LDSM_X4(a0, a1, a2, a3, a_base + aoff);
                #pragma unroll
                for (int nt = 0; nt < 4; ++nt)
                    MMA_FP16((&acc[(mt * 4 + nt) * 4]), a0, a1, a2, a3,
                             bh[nt][0], bh[nt][1]);
            }
        }
    };

    // ---- prologue: chunks 0 and 1 into stages 0 and 1 ----
    {
        float4 r0, r1;
        load_B_async(0, 0); CP_COMMIT();
        load_A_regs(0, r0, r1); store_A(0, r0, r1);
        load_B_async(1, 1); CP_COMMIT();
        load_A_regs(1, r0, r1); store_A(1, r0, r1);
        CP_WAIT1();                       // chunk 0 resident; chunk 1 in flight
        __syncthreads();
    }

    // ---- mainloop: 3-stage rotation ----
    #pragma unroll
    for (int kc = 0; kc < 8; ++kc) {
        const int st = kc % NSTAGE;
        float4 p0, p1;
        if (kc + 2 < 8) {
            const int st2 = (kc + 2) % NSTAGE;
            load_B_async(st2, kc + 2); CP_COMMIT();
            load_A_regs(kc + 2, p0, p1);
            compute(st);
            store_A(st2, p0, p1);
            CP_WAIT1();
        } else {
            compute(st);
            CP_WAIT0();
        }
        __syncthreads();
    }

    // ---- epilogue: bias + tanh + dot(score_w); smem cross-warp reduce ----
    #pragma unroll
    for (int mt = 0; mt < 4; ++mt) {
        float e0 = 0.0f, e1 = 0.0f;
        #pragma unroll
        for (int nt = 0; nt < 4; ++nt) {
            int col = wid * 32 + nt * 8 + (lane & 3) * 2;
            float b0 = s_bias[col], b1 = s_bias[col + 1];
            float w0 = s_sw[col],   w1 = s_sw[col + 1];
            float* d = &acc[(mt * 4 + nt) * 4];
            e0 = fmaf(tanh_acc(d[0] + b0), w0, e0);
            e0 = fmaf(tanh_acc(d[1] + b1), w1, e0);
            e1 = fmaf(tanh_acc(d[2] + b0), w0, e1);
            e1 = fmaf(tanh_acc(d[3] + b1), w1, e1);
        }
        e0 += __shfl_xor_sync(0xFFFFFFFFu, e0, 1);
        e0 += __shfl_xor_sync(0xFFFFFFFFu, e0, 2);
        e1 += __shfl_xor_sync(0xFFFFFFFFu, e1, 1);
        e1 += __shfl_xor_sync(0xFFFFFFFFu, e1, 2);
        if ((lane & 3) == 0) {
            int r = mt * 16 + (lane >> 2);
            s_part[wid * 64 + r]     = e0;
            s_part[wid * 64 + r + 8] = e1;
        }
    }
    __syncthreads();
    if (tid < 64) {
        float s = 0.0f;
        #pragma unroll
        for (int w = 0; w < 8; ++w) s += s_part[w * 64 + tid];
        g_e[m0 + tid] = s;
    }
}

// ---------------- kernel 2: parallel online-softmax scan (warp per column) ----------------
__global__ __launch_bounds__(256) void k_scan() {
    const int wid  = threadIdx.x >> 5;
    const int lane = threadIdx.x & 31;
    const int n    = blockIdx.x * 8 + wid;      // 128 blocks x 8 warps = 1024 cols
    const int t0   = lane * 16;

    float ev[16];
    #pragma unroll
    for (int k = 0; k < 16; ++k) ev[k] = g_e[(t0 + k) * N_DIM + n];

    float m = -INFINITY, s = 0.0f;
    #pragma unroll
    for (int k = 0; k < 16; ++k) {
        float e  = ev[k];
        float mn = fmaxf(m, e);
        s = s * __expf(m - mn) + __expf(e - mn);
        m = mn;
    }
    float im = m, is = s;
    #pragma unroll
    for (int off = 1; off < 32; off <<= 1) {
        float om = __shfl_up_sync(0xFFFFFFFFu, im, off);
        float os = __shfl_up_sync(0xFFFFFFFFu, is, off);
        if (lane >= off) {
            float mn = fmaxf(om, im);
            is = os * __expf(om - mn) + is * __expf(im - mn);
            im = mn;
        }
    }
    float Em = __shfl_up_sync(0xFFFFFFFFu, im, 1);
    float Es = __shfl_up_sync(0xFFFFFFFFu, is, 1);
    if (lane == 0) { Em = -INFINITY; Es = 0.0f; }

    float mc = Em, sc = Es;
    #pragma unroll
    for (int k = 0; k < 16; ++k) {
        float e   = ev[k];
        float mn  = fmaxf(mc, e);
        float al  = __expf(mc - mn);
        float p   = __expf(e - mn);
        float sn  = sc * al + p;
        float inv = 1.0f / sn;
        int idx = (t0 + k) * N_DIM + n;
        g_a[idx] = sc * al * inv;
        g_b[idx] = p * inv;
        mc = mn; sc = sn;
    }
}

// ---------------- kernel 3: streaming recurrence apply (scalar/thread) ----------------
// R8-verified version: one block (256 thr) per column n; one thread per (n, d).
__global__ __launch_bounds__(256) void k_apply(
    const float* __restrict__ H, float* __restrict__ out)
{
    const int n = blockIdx.x;
    const int d = threadIdx.x;                      // 0..255
    const size_t base  = (size_t)n * D_DIM + d;
    const size_t tstep = (size_t)N_DIM * D_DIM;     // per-t stride in floats

    float c = 0.0f;
    for (int t = 0; t < T_DIM; t += 8) {
        const int ia = t * N_DIM + n;
        float a[8], b[8], h[8];
        #pragma unroll
        for (int j = 0; j < 8; ++j) {
            a[j] = g_a[ia + j * N_DIM];             // uniform per block (broadcast)
            b[j] = g_b[ia + j * N_DIM];
        }
        #pragma unroll
        for (int j = 0; j < 8; ++j)
            h[j] = H[base + (size_t)(t + j) * tstep];
        #pragma unroll
        for (int j = 0; j < 8; ++j) {
            c = fmaf(a[j], c, b[j] * h[j]);
            out[base + (size_t)(t + j) * tstep] = c;
        }
    }
}

// ---------------- launch ----------------
extern "C" void kernel_launch(void* const* d_in, const int* in_sizes, int n_in,
                              void* d_out, int out_size) {
    const float* H       = (const float*)d_in[0];
    const float* fc_w    = (const float*)d_in[1];
    const float* fc_b    = (const float*)d_in[2];
    const float* score_w = (const float*)d_in[3];
    float* out = (float*)d_out;

    cudaFuncSetAttribute(k_score, cudaFuncAttributeMaxDynamicSharedMemorySize, SMEM_TOTAL);

    k_bconv<<<D_DIM * D_DIM / 256, 256>>>(fc_w);
    k_score<<<TN / BM, 256, SMEM_TOTAL>>>(H, fc_b, score_w);
    k_scan<<<128, 256>>>();
    k_apply<<<N_DIM, 256>>>(H, out);
}